// round 1
// baseline (speedup 1.0000x reference)
#include <cuda_runtime.h>
#include <cuda_bf16.h>
#include <math.h>

// Problem constants
#define BB 2
#define SS 4096
#define PP 1024
#define DD 1024
#define HH 16
#define DH 64

// Scratch (device globals; no allocation allowed)
__device__ float g_q[BB * SS * DD];    // q projection  [8192,1024]
__device__ float g_k[BB * PP * DD];    // k projection  [2048,1024]
__device__ float g_v[BB * PP * DD];    // v projection  [2048,1024]
__device__ float g_ao[BB * SS * DD];   // attention out [8192,1024]
__device__ int   g_pidx[BB * SS];      // cumsum of boundaries

// ---------------------------------------------------------------------------
// SGEMM: C[M,N] = A[M,K] @ W[N,K]^T + bias[N]   (both A and W K-contiguous)
// 128x128 tile, BK=8, 256 threads, 8x8 per-thread microtile.
// ---------------------------------------------------------------------------
__global__ __launch_bounds__(256)
void sgemm_bias_kernel(const float* __restrict__ A, const float* __restrict__ W,
                       const float* __restrict__ bias, float* __restrict__ C,
                       int M, int N, int K)
{
    __shared__ float As[8][128];
    __shared__ float Bs[8][128];

    const int tid = threadIdx.x;
    const int bx = blockIdx.x;   // N tile
    const int by = blockIdx.y;   // M tile
    const int tx = tid & 15;
    const int ty = tid >> 4;

    const float* Ab = A + (size_t)by * 128 * K;
    const float* Wb = W + (size_t)bx * 128 * K;

    const int lr = tid >> 1;        // 0..127
    const int lk = (tid & 1) * 4;   // 0 or 4

    float acc[8][8];
#pragma unroll
    for (int i = 0; i < 8; i++)
#pragma unroll
        for (int j = 0; j < 8; j++) acc[i][j] = 0.f;

    for (int k0 = 0; k0 < K; k0 += 8) {
        float4 a4 = *(const float4*)&Ab[(size_t)lr * K + k0 + lk];
        float4 b4 = *(const float4*)&Wb[(size_t)lr * K + k0 + lk];
        As[lk + 0][lr] = a4.x; As[lk + 1][lr] = a4.y;
        As[lk + 2][lr] = a4.z; As[lk + 3][lr] = a4.w;
        Bs[lk + 0][lr] = b4.x; Bs[lk + 1][lr] = b4.y;
        Bs[lk + 2][lr] = b4.z; Bs[lk + 3][lr] = b4.w;
        __syncthreads();

#pragma unroll
        for (int kk = 0; kk < 8; kk++) {
            float ra[8], rb[8];
#pragma unroll
            for (int i = 0; i < 8; i++) ra[i] = As[kk][ty * 8 + i];
#pragma unroll
            for (int j = 0; j < 8; j++) rb[j] = Bs[kk][tx * 8 + j];
#pragma unroll
            for (int i = 0; i < 8; i++)
#pragma unroll
                for (int j = 0; j < 8; j++)
                    acc[i][j] = fmaf(ra[i], rb[j], acc[i][j]);
        }
        __syncthreads();
    }

    // epilogue with bias, float4 stores
    const int cbase = bx * 128 + tx * 8;
    float4 bv0 = *(const float4*)&bias[cbase];
    float4 bv1 = *(const float4*)&bias[cbase + 4];
#pragma unroll
    for (int i = 0; i < 8; i++) {
        int row = by * 128 + ty * 8 + i;
        float4 o0 = make_float4(acc[i][0] + bv0.x, acc[i][1] + bv0.y,
                                acc[i][2] + bv0.z, acc[i][3] + bv0.w);
        float4 o1 = make_float4(acc[i][4] + bv1.x, acc[i][5] + bv1.y,
                                acc[i][6] + bv1.z, acc[i][7] + bv1.w);
        *(float4*)&C[(size_t)row * N + cbase] = o0;
        *(float4*)&C[(size_t)row * N + cbase + 4] = o1;
    }
}

// ---------------------------------------------------------------------------
// Inclusive scan of patch boundaries per batch: pidx[b,s] = cumsum(bnd[b,:s+1])
// One block per batch, 1024 threads x 4 elems.
// ---------------------------------------------------------------------------
__global__ void scan_kernel(const int* __restrict__ bnd, int* __restrict__ pidx)
{
    __shared__ int tsum[1024];
    const int b = blockIdx.x;
    const int t = threadIdx.x;
    const int base = b * SS + t * 4;

    int v0 = bnd[base + 0];
    int v1 = bnd[base + 1];
    int v2 = bnd[base + 2];
    int v3 = bnd[base + 3];
    int c0 = v0, c1 = c0 + v1, c2 = c1 + v2, c3 = c2 + v3;

    tsum[t] = c3;
    __syncthreads();
    for (int off = 1; off < 1024; off <<= 1) {
        int x = (t >= off) ? tsum[t - off] : 0;
        __syncthreads();
        tsum[t] += x;
        __syncthreads();
    }
    int excl = tsum[t] - c3;
    pidx[base + 0] = excl + c0;
    pidx[base + 1] = excl + c1;
    pidx[base + 2] = excl + c2;
    pidx[base + 3] = excl + c3;
}

// ---------------------------------------------------------------------------
// Flash-attention (fp32): block = 64 queries of one (b,h), 256 threads.
// Online softmax over 16 key tiles of 64; early-exit past the max patch idx.
// Thread t: q = t/4, owns 16 scores (j-range) and 16 output dims (d-range).
// ---------------------------------------------------------------------------
#define KS_STRIDE 68
#define PS_STRIDE 68
#define ATTN_SMEM_FLOATS (64*64 + 64*KS_STRIDE + 64*64 + 64*PS_STRIDE)
#define ATTN_SMEM_BYTES (ATTN_SMEM_FLOATS * 4)

__global__ __launch_bounds__(256)
void attn_kernel(const float* __restrict__ Q, const float* __restrict__ K,
                 const float* __restrict__ V, const int* __restrict__ pidx,
                 float* __restrict__ O)
{
    extern __shared__ float sm[];
    float* Qs = sm;                    // [64][64]
    float* Ks = Qs + 64 * 64;          // [d][j], stride 68 (transposed)
    float* Vs = Ks + 64 * KS_STRIDE;   // [j][d]
    float* Ps = Vs + 64 * 64;          // [q][j], stride 68

    const int qt = blockIdx.x;
    const int h  = blockIdx.y;
    const int b  = blockIdx.z;
    const int tid = threadIdx.x;
    const int q  = tid >> 2;        // 0..63
    const int jg = tid & 3;         // 0..3
    const int d0 = jg * 16;
    const int s0 = qt * 64;

    // load Q tile
    for (int i = tid; i < 64 * 16; i += 256) {
        int r = i >> 4, c4 = (i & 15) << 2;
        float4 v4 = *(const float4*)&Q[((size_t)(b * SS + s0 + r)) * DD + h * DH + c4];
        *(float4*)&Qs[r * 64 + c4] = v4;
    }

    const int mypidx  = pidx[b * SS + s0 + q];
    const int tilemax = pidx[b * SS + s0 + 63];   // cumsum nondecreasing

    float m = -1e30f, l = 0.f;
    float acc[16];
#pragma unroll
    for (int i = 0; i < 16; i++) acc[i] = 0.f;

    int ntiles = tilemax / 64 + 1;
    if (ntiles > 16) ntiles = 16;

    for (int t = 0; t < ntiles; ++t) {
        const int j0 = t * 64;
        __syncthreads();   // prior PV done before overwriting Ks/Vs (and Q load on t=0)

        // load K (transposed into [d][j]) and V ([j][d])
        for (int i = tid; i < 64 * 16; i += 256) {
            int j = i >> 4, c4 = (i & 15) << 2;
            const size_t gro = ((size_t)(b * PP + j0 + j)) * DD + h * DH + c4;
            float4 kv = *(const float4*)&K[gro];
            Ks[(c4 + 0) * KS_STRIDE + j] = kv.x;
            Ks[(c4 + 1) * KS_STRIDE + j] = kv.y;
            Ks[(c4 + 2) * KS_STRIDE + j] = kv.z;
            Ks[(c4 + 3) * KS_STRIDE + j] = kv.w;
            float4 vv = *(const float4*)&V[gro];
            *(float4*)&Vs[j * 64 + c4] = vv;
        }
        __syncthreads();

        // scores: s[q][j0 + jg*16 + jj]
        float sc[16];
#pragma unroll
        for (int jj = 0; jj < 16; jj++) sc[jj] = 0.f;
#pragma unroll 16
        for (int d = 0; d < 64; d++) {
            float qv = Qs[q * 64 + d];
            const float* kr = &Ks[d * KS_STRIDE + jg * 16];
#pragma unroll
            for (int jj = 0; jj < 16; jj++)
                sc[jj] = fmaf(qv, kr[jj], sc[jj]);
        }

        // scale + boundary mask: patch j allowed iff j <= pidx[query]
        const float scale = 0.125f;  // 1/sqrt(64)
#pragma unroll
        for (int jj = 0; jj < 16; jj++) {
            int jglob = j0 + jg * 16 + jj;
            sc[jj] = (jglob <= mypidx) ? sc[jj] * scale : -1e30f;
        }

        // row max (16 local + across the 4 lanes sharing this q; same warp)
        float tm = sc[0];
#pragma unroll
        for (int jj = 1; jj < 16; jj++) tm = fmaxf(tm, sc[jj]);
        tm = fmaxf(tm, __shfl_xor_sync(0xffffffffu, tm, 1));
        tm = fmaxf(tm, __shfl_xor_sync(0xffffffffu, tm, 2));

        float mnew = fmaxf(m, tm);
        float alpha = __expf(m - mnew);
        float ls = 0.f;
#pragma unroll
        for (int jj = 0; jj < 16; jj++) {
            float p = __expf(sc[jj] - mnew);
            sc[jj] = p;
            ls += p;
        }
        ls += __shfl_xor_sync(0xffffffffu, ls, 1);
        ls += __shfl_xor_sync(0xffffffffu, ls, 2);

        m = mnew;
        l = l * alpha + ls;
#pragma unroll
        for (int i = 0; i < 16; i++) acc[i] *= alpha;

        // write P tile
        *(float4*)&Ps[q * PS_STRIDE + jg * 16 + 0]  = make_float4(sc[0], sc[1], sc[2], sc[3]);
        *(float4*)&Ps[q * PS_STRIDE + jg * 16 + 4]  = make_float4(sc[4], sc[5], sc[6], sc[7]);
        *(float4*)&Ps[q * PS_STRIDE + jg * 16 + 8]  = make_float4(sc[8], sc[9], sc[10], sc[11]);
        *(float4*)&Ps[q * PS_STRIDE + jg * 16 + 12] = make_float4(sc[12], sc[13], sc[14], sc[15]);
        __syncthreads();

        // PV: acc[d0+i] += sum_j P[q][j] * V[j][d0+i]
#pragma unroll 16
        for (int j = 0; j < 64; j++) {
            float p = Ps[q * PS_STRIDE + j];
            const float* vr = &Vs[j * 64 + d0];
#pragma unroll
            for (int i = 0; i < 16; i++)
                acc[i] = fmaf(p, vr[i], acc[i]);
        }
    }

    // epilogue
    float inv = 1.f / l;
#pragma unroll
    for (int i = 0; i < 16; i++) acc[i] *= inv;

    float* orow = &O[((size_t)(b * SS + s0 + q)) * DD + h * DH + d0];
    *(float4*)&orow[0]  = make_float4(acc[0], acc[1], acc[2], acc[3]);
    *(float4*)&orow[4]  = make_float4(acc[4], acc[5], acc[6], acc[7]);
    *(float4*)&orow[8]  = make_float4(acc[8], acc[9], acc[10], acc[11]);
    *(float4*)&orow[12] = make_float4(acc[12], acc[13], acc[14], acc[15]);
}

// ---------------------------------------------------------------------------
extern "C" void kernel_launch(void* const* d_in, const int* in_sizes, int n_in,
                              void* d_out, int out_size)
{
    const float* queries = (const float*)d_in[0];
    const float* preps   = (const float*)d_in[1];
    const int*   bnd     = (const int*)d_in[2];
    const float* wq      = (const float*)d_in[3];
    const float* wk      = (const float*)d_in[4];
    const float* wv      = (const float*)d_in[5];
    const float* wo      = (const float*)d_in[6];
    const float* bq      = (const float*)d_in[7];
    const float* bk      = (const float*)d_in[8];
    const float* bv      = (const float*)d_in[9];
    const float* bo      = (const float*)d_in[10];
    float* out = (float*)d_out;

    float *gq, *gk, *gv, *gao;
    int* gpidx;
    cudaGetSymbolAddress((void**)&gq, g_q);
    cudaGetSymbolAddress((void**)&gk, g_k);
    cudaGetSymbolAddress((void**)&gv, g_v);
    cudaGetSymbolAddress((void**)&gao, g_ao);
    cudaGetSymbolAddress((void**)&gpidx, g_pidx);

    cudaFuncSetAttribute(attn_kernel, cudaFuncAttributeMaxDynamicSharedMemorySize,
                         ATTN_SMEM_BYTES);

    // projections
    sgemm_bias_kernel<<<dim3(DD / 128, (BB * SS) / 128), 256>>>(queries, wq, bq, gq,
                                                                BB * SS, DD, DD);
    sgemm_bias_kernel<<<dim3(DD / 128, (BB * PP) / 128), 256>>>(preps, wk, bk, gk,
                                                                BB * PP, DD, DD);
    sgemm_bias_kernel<<<dim3(DD / 128, (BB * PP) / 128), 256>>>(preps, wv, bv, gv,
                                                                BB * PP, DD, DD);
    // boundary cumsum
    scan_kernel<<<BB, 1024>>>(bnd, gpidx);

    // fused masked attention
    attn_kernel<<<dim3(SS / 64, HH, BB), 256, ATTN_SMEM_BYTES>>>(gq, gk, gv, gpidx, gao);

    // output projection -> d_out
    sgemm_bias_kernel<<<dim3(DD / 128, (BB * SS) / 128), 256>>>(gao, wo, bo, out,
                                                                BB * SS, DD, DD);
}

// round 4
// speedup vs baseline: 1.2505x; 1.2505x over previous
#include <cuda_runtime.h>
#include <cuda_bf16.h>
#include <math.h>
#include <stdint.h>

// Problem constants
#define BB 2
#define SS 4096
#define PP 1024
#define DD 1024
#define HH 16
#define DH 64

// Scratch (device globals; no allocation allowed)
__device__ float g_q[BB * SS * DD];    // q projection  [8192,1024]
__device__ float g_k[BB * PP * DD];    // k projection  [2048,1024]
__device__ float g_v[BB * PP * DD];    // v projection  [2048,1024]
__device__ float g_ao[BB * SS * DD];   // attention out [8192,1024]
__device__ int   g_pidx[BB * SS];      // cumsum of boundaries

// ===========================================================================
// helpers: cp.async + tf32 mma.sync (portable sm_80+ ISA; compiles at sm_103)
// ===========================================================================
__device__ __forceinline__ uint32_t smem_u32(const void* p) {
    uint32_t a;
    asm("{ .reg .u64 t; cvta.to.shared.u64 t, %1; cvt.u32.u64 %0, t; }"
        : "=r"(a) : "l"(p));
    return a;
}

#define CP_ASYNC16(dst, src) \
    asm volatile("cp.async.cg.shared.global [%0], [%1], 16;" \
                 :: "r"(dst), "l"(src) : "memory")
#define CP_ASYNC_COMMIT() asm volatile("cp.async.commit_group;" ::: "memory")
#define CP_ASYNC_WAIT1()  asm volatile("cp.async.wait_group 1;" ::: "memory")
#define CP_ASYNC_WAIT0()  asm volatile("cp.async.wait_group 0;" ::: "memory")

__device__ __forceinline__ uint32_t f2tf32(float f) {
    uint32_t u;
    asm("cvt.rna.tf32.f32 %0, %1;" : "=r"(u) : "f"(f));
    return u;
}

__device__ __forceinline__ void mma_m16n8k8_tf32(float* c, const uint32_t* a,
                                                 const uint32_t* b) {
    asm volatile(
        "mma.sync.aligned.m16n8k8.row.col.f32.tf32.tf32.f32 "
        "{%0,%1,%2,%3}, {%4,%5,%6,%7}, {%8,%9}, {%0,%1,%2,%3};"
        : "+f"(c[0]), "+f"(c[1]), "+f"(c[2]), "+f"(c[3])
        : "r"(a[0]), "r"(a[1]), "r"(a[2]), "r"(a[3]), "r"(b[0]), "r"(b[1]));
}

// ===========================================================================
// tf32 mma.sync GEMM: C[M,N] = A[M,K] @ W[N,K]^T + bias[N]
// 128x128 block tile, BK=32, 256 threads (8 warps, 4x2), warp tile 32x64.
// Double-buffered cp.async. SMEM rows padded to 36 floats (conflict-free
// fragment loads: bank = (4g + t) % 32, distinct across the warp).
// ===========================================================================
#define GBM 128
#define GBN 128
#define GBK 32
#define GPAD 36
#define GEMM_SMEM (2 * 2 * GBM * GPAD * 4)   // 73728 B

__global__ __launch_bounds__(256, 1)
void tf32_mma_gemm(const float* __restrict__ A, const float* __restrict__ W,
                   const float* __restrict__ bias, float* __restrict__ C,
                   int M, int N, int K)
{
    extern __shared__ float smem[];
    float* As = smem;                    // [2][128][36]
    float* Bs = smem + 2 * GBM * GPAD;   // [2][128][36]

    const int tid = threadIdx.x;
    const int lane = tid & 31;
    const int wid = tid >> 5;
    const int wm = wid & 3;    // 0..3 -> M offset wm*32
    const int wn = wid >> 2;   // 0..1 -> N offset wn*64
    const int g = lane >> 2;   // 0..7
    const int t = lane & 3;    // 0..3
    const int bx = blockIdx.x; // N tile
    const int by = blockIdx.y; // M tile

    float acc[2][8][4];
#pragma unroll
    for (int mt = 0; mt < 2; mt++)
#pragma unroll
        for (int nt = 0; nt < 8; nt++)
#pragma unroll
            for (int i = 0; i < 4; i++) acc[mt][nt][i] = 0.f;

    const float* gAbase = A + (size_t)by * GBM * K;
    const float* gWbase = W + (size_t)bx * GBN * K;

    // tile loader: 128 rows x 32 floats for both A and B = 512 cp.async of 16B
    auto load_tile = [&](int step) {
        const int buf = step & 1;
        const float* gA = gAbase + step * GBK;
        const float* gW = gWbase + step * GBK;
        float* sa = As + buf * GBM * GPAD;
        float* sb = Bs + buf * GBM * GPAD;
#pragma unroll
        for (int it = 0; it < 4; it++) {
            int c = tid + it * 256;
            int row = c >> 3, col = (c & 7) * 4;
            CP_ASYNC16(smem_u32(sa + row * GPAD + col), gA + (size_t)row * K + col);
            CP_ASYNC16(smem_u32(sb + row * GPAD + col), gW + (size_t)row * K + col);
        }
        CP_ASYNC_COMMIT();
    };

    const int nsteps = K / GBK;
    load_tile(0);

    for (int i = 0; i < nsteps; i++) {
        const int buf = i & 1;
        if (i + 1 < nsteps) { load_tile(i + 1); CP_ASYNC_WAIT1(); }
        else                { CP_ASYNC_WAIT0(); }
        __syncthreads();

        const float* sa = As + buf * GBM * GPAD + (wm * 32) * GPAD;
        const float* sb = Bs + buf * GBM * GPAD + (wn * 64) * GPAD;

#pragma unroll
        for (int ks = 0; ks < 4; ks++) {
            const int k0 = ks * 8;
            uint32_t af[2][4], bf[8][2];
#pragma unroll
            for (int mt = 0; mt < 2; mt++) {
                const float* p = sa + (mt * 16 + g) * GPAD + k0 + t;
                af[mt][0] = f2tf32(p[0]);            // (g,      t)
                af[mt][2] = f2tf32(p[4]);            // (g,      t+4)
                af[mt][1] = f2tf32(p[8 * GPAD]);     // (g+8,    t)
                af[mt][3] = f2tf32(p[8 * GPAD + 4]); // (g+8,    t+4)
            }
#pragma unroll
            for (int nt = 0; nt < 8; nt++) {
                const float* q = sb + (nt * 8 + g) * GPAD + k0 + t;
                bf[nt][0] = f2tf32(q[0]);   // (k=t,   n=g)
                bf[nt][1] = f2tf32(q[4]);   // (k=t+4, n=g)
            }
#pragma unroll
            for (int mt = 0; mt < 2; mt++)
#pragma unroll
                for (int nt = 0; nt < 8; nt++)
                    mma_m16n8k8_tf32(acc[mt][nt], af[mt], bf[nt]);
        }
        __syncthreads();
    }

    // epilogue: bias + store (float2 per fragment row pair)
#pragma unroll
    for (int mt = 0; mt < 2; mt++) {
        int r = by * GBM + wm * 32 + mt * 16 + g;
#pragma unroll
        for (int nt = 0; nt < 8; nt++) {
            int col = bx * GBN + wn * 64 + nt * 8 + 2 * t;
            float2 bv = *(const float2*)&bias[col];
            float2 o0 = make_float2(acc[mt][nt][0] + bv.x, acc[mt][nt][1] + bv.y);
            float2 o1 = make_float2(acc[mt][nt][2] + bv.x, acc[mt][nt][3] + bv.y);
            *(float2*)&C[(size_t)r * N + col] = o0;
            *(float2*)&C[(size_t)(r + 8) * N + col] = o1;
        }
    }
}

// ---------------------------------------------------------------------------
// Inclusive scan of patch boundaries per batch
// ---------------------------------------------------------------------------
__global__ void scan_kernel(const int* __restrict__ bnd, int* __restrict__ pidx)
{
    __shared__ int tsum[1024];
    const int b = blockIdx.x;
    const int t = threadIdx.x;
    const int base = b * SS + t * 4;

    int v0 = bnd[base + 0];
    int v1 = bnd[base + 1];
    int v2 = bnd[base + 2];
    int v3 = bnd[base + 3];
    int c0 = v0, c1 = c0 + v1, c2 = c1 + v2, c3 = c2 + v3;

    tsum[t] = c3;
    __syncthreads();
    for (int off = 1; off < 1024; off <<= 1) {
        int x = (t >= off) ? tsum[t - off] : 0;
        __syncthreads();
        tsum[t] += x;
        __syncthreads();
    }
    int excl = tsum[t] - c3;
    pidx[base + 0] = excl + c0;
    pidx[base + 1] = excl + c1;
    pidx[base + 2] = excl + c2;
    pidx[base + 3] = excl + c3;
}

// ---------------------------------------------------------------------------
// Flash-attention (fp32), unchanged from Round 1
// ---------------------------------------------------------------------------
#define KS_STRIDE 68
#define PS_STRIDE 68
#define ATTN_SMEM_FLOATS (64*64 + 64*KS_STRIDE + 64*64 + 64*PS_STRIDE)
#define ATTN_SMEM_BYTES (ATTN_SMEM_FLOATS * 4)

__global__ __launch_bounds__(256)
void attn_kernel(const float* __restrict__ Q, const float* __restrict__ K,
                 const float* __restrict__ V, const int* __restrict__ pidx,
                 float* __restrict__ O)
{
    extern __shared__ float sm[];
    float* Qs = sm;                    // [64][64]
    float* Ks = Qs + 64 * 64;          // [d][j], stride 68 (transposed)
    float* Vs = Ks + 64 * KS_STRIDE;   // [j][d]
    float* Ps = Vs + 64 * 64;          // [q][j], stride 68

    const int qt = blockIdx.x;
    const int h  = blockIdx.y;
    const int b  = blockIdx.z;
    const int tid = threadIdx.x;
    const int q  = tid >> 2;        // 0..63
    const int jg = tid & 3;         // 0..3
    const int d0 = jg * 16;
    const int s0 = qt * 64;

    for (int i = tid; i < 64 * 16; i += 256) {
        int r = i >> 4, c4 = (i & 15) << 2;
        float4 v4 = *(const float4*)&Q[((size_t)(b * SS + s0 + r)) * DD + h * DH + c4];
        *(float4*)&Qs[r * 64 + c4] = v4;
    }

    const int mypidx  = pidx[b * SS + s0 + q];
    const int tilemax = pidx[b * SS + s0 + 63];

    float m = -1e30f, l = 0.f;
    float acc[16];
#pragma unroll
    for (int i = 0; i < 16; i++) acc[i] = 0.f;

    int ntiles = tilemax / 64 + 1;
    if (ntiles > 16) ntiles = 16;

    for (int t = 0; t < ntiles; ++t) {
        const int j0 = t * 64;
        __syncthreads();

        for (int i = tid; i < 64 * 16; i += 256) {
            int j = i >> 4, c4 = (i & 15) << 2;
            const size_t gro = ((size_t)(b * PP + j0 + j)) * DD + h * DH + c4;
            float4 kv = *(const float4*)&K[gro];
            Ks[(c4 + 0) * KS_STRIDE + j] = kv.x;
            Ks[(c4 + 1) * KS_STRIDE + j] = kv.y;
            Ks[(c4 + 2) * KS_STRIDE + j] = kv.z;
            Ks[(c4 + 3) * KS_STRIDE + j] = kv.w;
            float4 vv = *(const float4*)&V[gro];
            *(float4*)&Vs[j * 64 + c4] = vv;
        }
        __syncthreads();

        float sc[16];
#pragma unroll
        for (int jj = 0; jj < 16; jj++) sc[jj] = 0.f;
#pragma unroll 16
        for (int d = 0; d < 64; d++) {
            float qv = Qs[q * 64 + d];
            const float* kr = &Ks[d * KS_STRIDE + jg * 16];
#pragma unroll
            for (int jj = 0; jj < 16; jj++)
                sc[jj] = fmaf(qv, kr[jj], sc[jj]);
        }

        const float scale = 0.125f;
#pragma unroll
        for (int jj = 0; jj < 16; jj++) {
            int jglob = j0 + jg * 16 + jj;
            sc[jj] = (jglob <= mypidx) ? sc[jj] * scale : -1e30f;
        }

        float tm = sc[0];
#pragma unroll
        for (int jj = 1; jj < 16; jj++) tm = fmaxf(tm, sc[jj]);
        tm = fmaxf(tm, __shfl_xor_sync(0xffffffffu, tm, 1));
        tm = fmaxf(tm, __shfl_xor_sync(0xffffffffu, tm, 2));

        float mnew = fmaxf(m, tm);
        float alpha = __expf(m - mnew);
        float ls = 0.f;
#pragma unroll
        for (int jj = 0; jj < 16; jj++) {
            float p = __expf(sc[jj] - mnew);
            sc[jj] = p;
            ls += p;
        }
        ls += __shfl_xor_sync(0xffffffffu, ls, 1);
        ls += __shfl_xor_sync(0xffffffffu, ls, 2);

        m = mnew;
        l = l * alpha + ls;
#pragma unroll
        for (int i = 0; i < 16; i++) acc[i] *= alpha;

        *(float4*)&Ps[q * PS_STRIDE + jg * 16 + 0]  = make_float4(sc[0], sc[1], sc[2], sc[3]);
        *(float4*)&Ps[q * PS_STRIDE + jg * 16 + 4]  = make_float4(sc[4], sc[5], sc[6], sc[7]);
        *(float4*)&Ps[q * PS_STRIDE + jg * 16 + 8]  = make_float4(sc[8], sc[9], sc[10], sc[11]);
        *(float4*)&Ps[q * PS_STRIDE + jg * 16 + 12] = make_float4(sc[12], sc[13], sc[14], sc[15]);
        __syncthreads();

#pragma unroll 16
        for (int j = 0; j < 64; j++) {
            float p = Ps[q * PS_STRIDE + j];
            const float* vr = &Vs[j * 64 + d0];
#pragma unroll
            for (int i = 0; i < 16; i++)
                acc[i] = fmaf(p, vr[i], acc[i]);
        }
    }

    float inv = 1.f / l;
#pragma unroll
    for (int i = 0; i < 16; i++) acc[i] *= inv;

    float* orow = &O[((size_t)(b * SS + s0 + q)) * DD + h * DH + d0];
    *(float4*)&orow[0]  = make_float4(acc[0], acc[1], acc[2], acc[3]);
    *(float4*)&orow[4]  = make_float4(acc[4], acc[5], acc[6], acc[7]);
    *(float4*)&orow[8]  = make_float4(acc[8], acc[9], acc[10], acc[11]);
    *(float4*)&orow[12] = make_float4(acc[12], acc[13], acc[14], acc[15]);
}

// ---------------------------------------------------------------------------
extern "C" void kernel_launch(void* const* d_in, const int* in_sizes, int n_in,
                              void* d_out, int out_size)
{
    const float* queries = (const float*)d_in[0];
    const float* preps   = (const float*)d_in[1];
    const int*   bnd     = (const int*)d_in[2];
    const float* wq      = (const float*)d_in[3];
    const float* wk      = (const float*)d_in[4];
    const float* wv      = (const float*)d_in[5];
    const float* wo      = (const float*)d_in[6];
    const float* bq      = (const float*)d_in[7];
    const float* bk      = (const float*)d_in[8];
    const float* bv      = (const float*)d_in[9];
    const float* bo      = (const float*)d_in[10];
    float* out = (float*)d_out;

    float *gq, *gk, *gv, *gao;
    int* gpidx;
    cudaGetSymbolAddress((void**)&gq, g_q);
    cudaGetSymbolAddress((void**)&gk, g_k);
    cudaGetSymbolAddress((void**)&gv, g_v);
    cudaGetSymbolAddress((void**)&gao, g_ao);
    cudaGetSymbolAddress((void**)&gpidx, g_pidx);

    cudaFuncSetAttribute(tf32_mma_gemm, cudaFuncAttributeMaxDynamicSharedMemorySize,
                         GEMM_SMEM);
    cudaFuncSetAttribute(attn_kernel, cudaFuncAttributeMaxDynamicSharedMemorySize,
                         ATTN_SMEM_BYTES);

    // projections (tf32 mma.sync)
    tf32_mma_gemm<<<dim3(DD / GBN, (BB * SS) / GBM), 256, GEMM_SMEM>>>(
        queries, wq, bq, gq, BB * SS, DD, DD);
    tf32_mma_gemm<<<dim3(DD / GBN, (BB * PP) / GBM), 256, GEMM_SMEM>>>(
        preps, wk, bk, gk, BB * PP, DD, DD);
    tf32_mma_gemm<<<dim3(DD / GBN, (BB * PP) / GBM), 256, GEMM_SMEM>>>(
        preps, wv, bv, gv, BB * PP, DD, DD);

    // boundary cumsum
    scan_kernel<<<BB, 1024>>>(bnd, gpidx);

    // fused masked attention (fp32)
    attn_kernel<<<dim3(SS / 64, HH, BB), 256, ATTN_SMEM_BYTES>>>(gq, gk, gv, gpidx, gao);

    // output projection -> d_out (tf32 mma.sync)
    tf32_mma_gemm<<<dim3(DD / GBN, (BB * SS) / GBM), 256, GEMM_SMEM>>>(
        gao, wo, bo, out, BB * SS, DD, DD);
}

// round 6
// speedup vs baseline: 6.6978x; 5.3561x over previous
#include <cuda_runtime.h>
#include <cuda_bf16.h>
#include <math.h>
#include <stdint.h>

// Problem constants
#define BB 2
#define SS 4096
#define PP 1024
#define DD 1024
#define HH 16
#define DH 64

// Scratch (device globals; no allocation allowed)
__device__ float g_q[BB * SS * DD];    // q projection  [8192,1024]
__device__ float g_k[BB * PP * DD];    // k projection  [2048,1024]
__device__ float g_v[BB * PP * DD];    // v projection  [2048,1024]
__device__ float g_ao[BB * SS * DD];   // attention out [8192,1024]
__device__ int   g_pidx[BB * SS];      // cumsum of boundaries

// ===========================================================================
// helpers: cp.async + tf32 mma.sync (portable sm_80+ ISA; compiles at sm_103)
// ===========================================================================
__device__ __forceinline__ uint32_t smem_u32(const void* p) {
    uint32_t a;
    asm("{ .reg .u64 t; cvta.to.shared.u64 t, %1; cvt.u32.u64 %0, t; }"
        : "=r"(a) : "l"(p));
    return a;
}

#define CP_ASYNC16(dst, src) \
    asm volatile("cp.async.cg.shared.global [%0], [%1], 16;" \
                 :: "r"(dst), "l"(src) : "memory")
#define CP_ASYNC_COMMIT() asm volatile("cp.async.commit_group;" ::: "memory")
#define CP_ASYNC_WAIT1()  asm volatile("cp.async.wait_group 1;" ::: "memory")
#define CP_ASYNC_WAIT0()  asm volatile("cp.async.wait_group 0;" ::: "memory")

__device__ __forceinline__ uint32_t f2tf32(float f) {
    uint32_t u;
    asm("cvt.rna.tf32.f32 %0, %1;" : "=r"(u) : "f"(f));
    return u;
}
__device__ __forceinline__ float tf32r(float f) {
    return __uint_as_float(f2tf32(f));
}

__device__ __forceinline__ void mma_m16n8k8_tf32(float* c, const uint32_t* a,
                                                 const uint32_t* b) {
    asm volatile(
        "mma.sync.aligned.m16n8k8.row.col.f32.tf32.tf32.f32 "
        "{%0,%1,%2,%3}, {%4,%5,%6,%7}, {%8,%9}, {%0,%1,%2,%3};"
        : "+f"(c[0]), "+f"(c[1]), "+f"(c[2]), "+f"(c[3])
        : "r"(a[0]), "r"(a[1]), "r"(a[2]), "r"(a[3]), "r"(b[0]), "r"(b[1]));
}

// ===========================================================================
// tf32 mma.sync GEMM: C[M,N] = A[M,K] @ W[N,K]^T + bias[N]   (unchanged R4)
// ===========================================================================
#define GBM 128
#define GBN 128
#define GBK 32
#define GPAD 36
#define GEMM_SMEM (2 * 2 * GBM * GPAD * 4)   // 73728 B

__global__ __launch_bounds__(256, 1)
void tf32_mma_gemm(const float* __restrict__ A, const float* __restrict__ W,
                   const float* __restrict__ bias, float* __restrict__ C,
                   int M, int N, int K)
{
    extern __shared__ float smem[];
    float* As = smem;                    // [2][128][36]
    float* Bs = smem + 2 * GBM * GPAD;   // [2][128][36]

    const int tid = threadIdx.x;
    const int lane = tid & 31;
    const int wid = tid >> 5;
    const int wm = wid & 3;
    const int wn = wid >> 2;
    const int g = lane >> 2;
    const int t = lane & 3;
    const int bx = blockIdx.x;
    const int by = blockIdx.y;

    float acc[2][8][4];
#pragma unroll
    for (int mt = 0; mt < 2; mt++)
#pragma unroll
        for (int nt = 0; nt < 8; nt++)
#pragma unroll
            for (int i = 0; i < 4; i++) acc[mt][nt][i] = 0.f;

    const float* gAbase = A + (size_t)by * GBM * K;
    const float* gWbase = W + (size_t)bx * GBN * K;

    auto load_tile = [&](int step) {
        const int buf = step & 1;
        const float* gA = gAbase + step * GBK;
        const float* gW = gWbase + step * GBK;
        float* sa = As + buf * GBM * GPAD;
        float* sb = Bs + buf * GBM * GPAD;
#pragma unroll
        for (int it = 0; it < 4; it++) {
            int c = tid + it * 256;
            int row = c >> 3, col = (c & 7) * 4;
            CP_ASYNC16(smem_u32(sa + row * GPAD + col), gA + (size_t)row * K + col);
            CP_ASYNC16(smem_u32(sb + row * GPAD + col), gW + (size_t)row * K + col);
        }
        CP_ASYNC_COMMIT();
    };

    const int nsteps = K / GBK;
    load_tile(0);

    for (int i = 0; i < nsteps; i++) {
        const int buf = i & 1;
        if (i + 1 < nsteps) { load_tile(i + 1); CP_ASYNC_WAIT1(); }
        else                { CP_ASYNC_WAIT0(); }
        __syncthreads();

        const float* sa = As + buf * GBM * GPAD + (wm * 32) * GPAD;
        const float* sb = Bs + buf * GBM * GPAD + (wn * 64) * GPAD;

#pragma unroll
        for (int ks = 0; ks < 4; ks++) {
            const int k0 = ks * 8;
            uint32_t af[2][4], bf[8][2];
#pragma unroll
            for (int mt = 0; mt < 2; mt++) {
                const float* p = sa + (mt * 16 + g) * GPAD + k0 + t;
                af[mt][0] = f2tf32(p[0]);
                af[mt][2] = f2tf32(p[4]);
                af[mt][1] = f2tf32(p[8 * GPAD]);
                af[mt][3] = f2tf32(p[8 * GPAD + 4]);
            }
#pragma unroll
            for (int nt = 0; nt < 8; nt++) {
                const float* q = sb + (nt * 8 + g) * GPAD + k0 + t;
                bf[nt][0] = f2tf32(q[0]);
                bf[nt][1] = f2tf32(q[4]);
            }
#pragma unroll
            for (int mt = 0; mt < 2; mt++)
#pragma unroll
                for (int nt = 0; nt < 8; nt++)
                    mma_m16n8k8_tf32(acc[mt][nt], af[mt], bf[nt]);
        }
        __syncthreads();
    }

#pragma unroll
    for (int mt = 0; mt < 2; mt++) {
        int r = by * GBM + wm * 32 + mt * 16 + g;
#pragma unroll
        for (int nt = 0; nt < 8; nt++) {
            int col = bx * GBN + wn * 64 + nt * 8 + 2 * t;
            float2 bv = *(const float2*)&bias[col];
            float2 o0 = make_float2(acc[mt][nt][0] + bv.x, acc[mt][nt][1] + bv.y);
            float2 o1 = make_float2(acc[mt][nt][2] + bv.x, acc[mt][nt][3] + bv.y);
            *(float2*)&C[(size_t)r * N + col] = o0;
            *(float2*)&C[(size_t)(r + 8) * N + col] = o1;
        }
    }
}

// ---------------------------------------------------------------------------
// Inclusive scan of patch boundaries per batch
// ---------------------------------------------------------------------------
__global__ void scan_kernel(const int* __restrict__ bnd, int* __restrict__ pidx)
{
    __shared__ int tsum[1024];
    const int b = blockIdx.x;
    const int t = threadIdx.x;
    const int base = b * SS + t * 4;

    int v0 = bnd[base + 0];
    int v1 = bnd[base + 1];
    int v2 = bnd[base + 2];
    int v3 = bnd[base + 3];
    int c0 = v0, c1 = c0 + v1, c2 = c1 + v2, c3 = c2 + v3;

    tsum[t] = c3;
    __syncthreads();
    for (int off = 1; off < 1024; off <<= 1) {
        int x = (t >= off) ? tsum[t - off] : 0;
        __syncthreads();
        tsum[t] += x;
        __syncthreads();
    }
    int excl = tsum[t] - c3;
    pidx[base + 0] = excl + c0;
    pidx[base + 1] = excl + c1;
    pidx[base + 2] = excl + c2;
    pidx[base + 3] = excl + c3;
}

// ===========================================================================
// Flash-attention with tf32 mma.sync.
// Block = 128 queries of one (b,h), 256 threads (8 warps, 16 q-rows each).
// Key tiles of 64. Scores stay in C-fragments; softmax in registers.
// P round-trips through warp-private SMEM rows (syncwarp only).
// SMEM operands are tf32-rounded at store time. Pad 68 (= 4 mod 32) gives
// conflict-free fragment LDS.
// ===========================================================================
#define ABM 128
#define ABN 64
#define APAD 68
#define AKS_OFF (128 * APAD)
#define AVT_OFF (AKS_OFF + 64 * APAD)
#define APS_OFF (AVT_OFF + 64 * APAD)
#define ATTN2_SMEM ((APS_OFF + 128 * APAD) * 4)   // 104448 B

__global__ __launch_bounds__(256, 1)
void attn_mma_kernel(const float* __restrict__ Q, const float* __restrict__ Kg,
                     const float* __restrict__ Vg, const int* __restrict__ pidx,
                     float* __restrict__ O)
{
    extern __shared__ float sm[];
    float* Qs = sm;              // [128][APAD], tf32-rounded, pre-scaled
    float* Ks = sm + AKS_OFF;    // [64][APAD]   (j, d)
    float* Vt = sm + AVT_OFF;    // [64][APAD]   (d, j)  transposed
    float* Ps = sm + APS_OFF;    // [128][APAD]  warp-private rows

    const int qt = blockIdx.x;
    const int h  = blockIdx.y;
    const int b  = blockIdx.z;
    const int tid = threadIdx.x;
    const int lane = tid & 31;
    const int wid = tid >> 5;
    const int g = lane >> 2;
    const int t = lane & 3;
    const int s0 = qt * ABM;
    const int qbase = wid * 16;

    // ---- load Q tile (scale folded in, tf32-rounded) ----
    for (int i = tid; i < 128 * 16; i += 256) {
        int r = i >> 4, c4 = (i & 15) << 2;
        float4 v = *(const float4*)&Q[((size_t)(b * SS + s0 + r)) * DD + h * DH + c4];
        v.x = tf32r(v.x * 0.125f);
        v.y = tf32r(v.y * 0.125f);
        v.z = tf32r(v.z * 0.125f);
        v.w = tf32r(v.w * 0.125f);
        *(float4*)&Qs[r * APAD + c4] = v;
    }

    const int prow0 = pidx[b * SS + s0 + qbase + g];
    const int prow1 = pidx[b * SS + s0 + qbase + g + 8];
    const int tilemax = pidx[b * SS + s0 + ABM - 1];

    float m0 = -1e30f, m1 = -1e30f, l0 = 0.f, l1 = 0.f;
    float acc_o[8][4];
#pragma unroll
    for (int nt = 0; nt < 8; nt++)
#pragma unroll
        for (int i = 0; i < 4; i++) acc_o[nt][i] = 0.f;

    int ntiles = tilemax / ABN + 1;
    if (ntiles > PP / ABN) ntiles = PP / ABN;

    for (int kt = 0; kt < ntiles; kt++) {
        const int j0 = kt * ABN;
        __syncthreads();   // prior PV done before overwriting Ks/Vt (covers Qs on kt=0)

        // ---- load K (row) and V (transposed) tiles, tf32-rounded ----
        for (int i = tid; i < 64 * 16; i += 256) {
            int j = i >> 4, c4 = (i & 15) << 2;
            const size_t gro = ((size_t)(b * PP + j0 + j)) * DD + h * DH + c4;
            float4 kv = *(const float4*)&Kg[gro];
            kv.x = tf32r(kv.x); kv.y = tf32r(kv.y);
            kv.z = tf32r(kv.z); kv.w = tf32r(kv.w);
            *(float4*)&Ks[j * APAD + c4] = kv;
            float4 vv = *(const float4*)&Vg[gro];
            Vt[(c4 + 0) * APAD + j] = tf32r(vv.x);
            Vt[(c4 + 1) * APAD + j] = tf32r(vv.y);
            Vt[(c4 + 2) * APAD + j] = tf32r(vv.z);
            Vt[(c4 + 3) * APAD + j] = tf32r(vv.w);
        }
        __syncthreads();

        // ---- QK^T: warp computes 16 q-rows x 64 keys ----
        float acc_s[8][4];
#pragma unroll
        for (int nt = 0; nt < 8; nt++)
#pragma unroll
            for (int i = 0; i < 4; i++) acc_s[nt][i] = 0.f;

#pragma unroll
        for (int ks = 0; ks < 8; ks++) {
            const int k0 = ks * 8;
            const float* ap = &Qs[(qbase + g) * APAD + k0 + t];
            uint32_t af[4];
            af[0] = __float_as_uint(ap[0]);
            af[1] = __float_as_uint(ap[8 * APAD]);
            af[2] = __float_as_uint(ap[4]);
            af[3] = __float_as_uint(ap[8 * APAD + 4]);
#pragma unroll
            for (int nt = 0; nt < 8; nt++) {
                const float* bp = &Ks[(nt * 8 + g) * APAD + k0 + t];
                uint32_t bf[2];
                bf[0] = __float_as_uint(bp[0]);
                bf[1] = __float_as_uint(bp[4]);
                mma_m16n8k8_tf32(acc_s[nt], af, bf);
            }
        }

        // ---- mask + tile max (C-layout: rows g/g+8, cols 2t,2t+1 per nt) ----
        float tm0 = -1e30f, tm1 = -1e30f;
#pragma unroll
        for (int nt = 0; nt < 8; nt++) {
            int c0 = j0 + nt * 8 + 2 * t, c1 = c0 + 1;
            acc_s[nt][0] = (c0 <= prow0) ? acc_s[nt][0] : -1e30f;
            acc_s[nt][1] = (c1 <= prow0) ? acc_s[nt][1] : -1e30f;
            acc_s[nt][2] = (c0 <= prow1) ? acc_s[nt][2] : -1e30f;
            acc_s[nt][3] = (c1 <= prow1) ? acc_s[nt][3] : -1e30f;
            tm0 = fmaxf(tm0, fmaxf(acc_s[nt][0], acc_s[nt][1]));
            tm1 = fmaxf(tm1, fmaxf(acc_s[nt][2], acc_s[nt][3]));
        }
        tm0 = fmaxf(tm0, __shfl_xor_sync(0xffffffffu, tm0, 1));
        tm0 = fmaxf(tm0, __shfl_xor_sync(0xffffffffu, tm0, 2));
        tm1 = fmaxf(tm1, __shfl_xor_sync(0xffffffffu, tm1, 1));
        tm1 = fmaxf(tm1, __shfl_xor_sync(0xffffffffu, tm1, 2));

        const float mn0 = fmaxf(m0, tm0), mn1 = fmaxf(m1, tm1);
        const float a0 = __expf(m0 - mn0), a1 = __expf(m1 - mn1);

        float ls0 = 0.f, ls1 = 0.f;
#pragma unroll
        for (int nt = 0; nt < 8; nt++) {
            acc_s[nt][0] = __expf(acc_s[nt][0] - mn0);
            acc_s[nt][1] = __expf(acc_s[nt][1] - mn0);
            acc_s[nt][2] = __expf(acc_s[nt][2] - mn1);
            acc_s[nt][3] = __expf(acc_s[nt][3] - mn1);
            ls0 += acc_s[nt][0] + acc_s[nt][1];
            ls1 += acc_s[nt][2] + acc_s[nt][3];
        }
        ls0 += __shfl_xor_sync(0xffffffffu, ls0, 1);
        ls0 += __shfl_xor_sync(0xffffffffu, ls0, 2);
        ls1 += __shfl_xor_sync(0xffffffffu, ls1, 1);
        ls1 += __shfl_xor_sync(0xffffffffu, ls1, 2);

        m0 = mn0; m1 = mn1;
        l0 = l0 * a0 + ls0;
        l1 = l1 * a1 + ls1;
#pragma unroll
        for (int nt = 0; nt < 8; nt++) {
            acc_o[nt][0] *= a0; acc_o[nt][1] *= a0;
            acc_o[nt][2] *= a1; acc_o[nt][3] *= a1;
        }

        // ---- write P (warp-private rows), tf32-rounded ----
#pragma unroll
        for (int nt = 0; nt < 8; nt++) {
            *(float2*)&Ps[(qbase + g) * APAD + nt * 8 + 2 * t] =
                make_float2(tf32r(acc_s[nt][0]), tf32r(acc_s[nt][1]));
            *(float2*)&Ps[(qbase + g + 8) * APAD + nt * 8 + 2 * t] =
                make_float2(tf32r(acc_s[nt][2]), tf32r(acc_s[nt][3]));
        }
        __syncwarp();

        // ---- P @ V: A = P rows (k = keys), B = Vt (n = d cols) ----
#pragma unroll
        for (int ks = 0; ks < 8; ks++) {
            const int k0 = ks * 8;
            const float* ap = &Ps[(qbase + g) * APAD + k0 + t];
            uint32_t af[4];
            af[0] = __float_as_uint(ap[0]);
            af[1] = __float_as_uint(ap[8 * APAD]);
            af[2] = __float_as_uint(ap[4]);
            af[3] = __float_as_uint(ap[8 * APAD + 4]);
#pragma unroll
            for (int nt = 0; nt < 8; nt++) {
                const float* bp = &Vt[(nt * 8 + g) * APAD + k0 + t];
                uint32_t bf[2];
                bf[0] = __float_as_uint(bp[0]);
                bf[1] = __float_as_uint(bp[4]);
                mma_m16n8k8_tf32(acc_o[nt], af, bf);
            }
        }
    }

    // ---- epilogue: normalize and store ----
    const float inv0 = 1.f / l0, inv1 = 1.f / l1;
    const size_t row0 = (size_t)(b * SS + s0 + qbase + g);
#pragma unroll
    for (int nt = 0; nt < 8; nt++) {
        int col = h * DH + nt * 8 + 2 * t;
        *(float2*)&O[row0 * DD + col] =
            make_float2(acc_o[nt][0] * inv0, acc_o[nt][1] * inv0);
        *(float2*)&O[(row0 + 8) * DD + col] =
            make_float2(acc_o[nt][2] * inv1, acc_o[nt][3] * inv1);
    }
}

// ---------------------------------------------------------------------------
extern "C" void kernel_launch(void* const* d_in, const int* in_sizes, int n_in,
                              void* d_out, int out_size)
{
    const float* queries = (const float*)d_in[0];
    const float* preps   = (const float*)d_in[1];
    const int*   bnd     = (const int*)d_in[2];
    const float* wq      = (const float*)d_in[3];
    const float* wk      = (const float*)d_in[4];
    const float* wv      = (const float*)d_in[5];
    const float* wo      = (const float*)d_in[6];
    const float* bq      = (const float*)d_in[7];
    const float* bk      = (const float*)d_in[8];
    const float* bv      = (const float*)d_in[9];
    const float* bo      = (const float*)d_in[10];
    float* out = (float*)d_out;

    float *gq, *gk, *gv, *gao;
    int* gpidx;
    cudaGetSymbolAddress((void**)&gq, g_q);
    cudaGetSymbolAddress((void**)&gk, g_k);
    cudaGetSymbolAddress((void**)&gv, g_v);
    cudaGetSymbolAddress((void**)&gao, g_ao);
    cudaGetSymbolAddress((void**)&gpidx, g_pidx);

    cudaFuncSetAttribute(tf32_mma_gemm, cudaFuncAttributeMaxDynamicSharedMemorySize,
                         GEMM_SMEM);
    cudaFuncSetAttribute(attn_mma_kernel, cudaFuncAttributeMaxDynamicSharedMemorySize,
                         ATTN2_SMEM);

    // projections (tf32 mma.sync)
    tf32_mma_gemm<<<dim3(DD / GBN, (BB * SS) / GBM), 256, GEMM_SMEM>>>(
        queries, wq, bq, gq, BB * SS, DD, DD);
    tf32_mma_gemm<<<dim3(DD / GBN, (BB * PP) / GBM), 256, GEMM_SMEM>>>(
        preps, wk, bk, gk, BB * PP, DD, DD);
    tf32_mma_gemm<<<dim3(DD / GBN, (BB * PP) / GBM), 256, GEMM_SMEM>>>(
        preps, wv, bv, gv, BB * PP, DD, DD);

    // boundary cumsum
    scan_kernel<<<BB, 1024>>>(bnd, gpidx);

    // fused masked attention (tf32 mma.sync)
    attn_mma_kernel<<<dim3(SS / ABM, HH, BB), 256, ATTN2_SMEM>>>(
        gq, gk, gv, gpidx, gao);

    // output projection -> d_out (tf32 mma.sync)
    tf32_mma_gemm<<<dim3(DD / GBN, (BB * SS) / GBM), 256, GEMM_SMEM>>>(
        gao, wo, bo, out, BB * SS, DD, DD);
}